// round 13
// baseline (speedup 1.0000x reference)
#include <cuda_runtime.h>
#include <cuda_bf16.h>

// NMS: B=32, N=2048, keep first R=100 surviving boxes (greedy, score-desc).
// pred: [B, N, 5] = (score, l, t, r, b);  out: [B, R, 3] = (t, r, b), zero-padded.

#define NMS_N      2048
#define NMS_R      100
#define NT         256
#define SEL_CAP    256
#define MAT_N      160
#define MAT_COLS   5
#define MAT_STRIDE 7
#define T_SEL      0.90f
#define U_TSEL     0x3F666666u   // bits of 0.90f

typedef unsigned long long ull;

__device__ __forceinline__ unsigned int float_to_ordered(float f) {
    unsigned int u = __float_as_uint(f);
    return (u & 0x80000000u) ? ~u : (u | 0x80000000u);
}

// suppress cb if inter(kb, cb) >= hh (= 0.5 * area(cb)); sentinel kb -> false
__device__ __forceinline__ bool iou_sup(const float4 kb, const float4 cb, float hh) {
    float il = fmaxf(kb.x, cb.x);
    float it = fmaxf(kb.y, cb.y);
    float ir = fminf(kb.z, cb.z);
    float ib = fminf(kb.w, cb.w);
    return fmaxf(0.0f, ir - il) * fmaxf(0.0f, ib - it) >= hh;
}
__device__ __forceinline__ void selset(float4& d, const float4 s, bool p) {
    d.x = p ? s.x : d.x; d.y = p ? s.y : d.y;
    d.z = p ? s.z : d.z; d.w = p ? s.w : d.w;
}

__global__ __launch_bounds__(NT, 1)
void nms_kernel(const float* __restrict__ pred, float* __restrict__ out) {
    // 16KB pool, aliased:
    //   fast path: selKeys32[256] (1KB @0) | supMat[160*7] (4.4KB @4KB)
    //   fallback : fullKeys[2048] (16KB)
    __shared__ __align__(16) ull pool[2048];
    unsigned*     selKeys32 = (unsigned*)pool;              // [256]
    unsigned int* supMat    = (unsigned int*)(pool + 512);  // [160*7], byte off 4KB
    ull*          fullKeys  = pool;

    __shared__ __align__(16) float4 sortedBoxes[SEL_CAP];
    __shared__ float sortedHalf[SEL_CAP];
    __shared__ __align__(16) float4 keptBoxes[136];
    __shared__ float keptVals[NMS_R * 3];
    __shared__ int   selCount, sh_nkept;

    const int b    = blockIdx.x;
    const int tid  = threadIdx.x;
    const int lane = tid & 31;
    const int w    = tid >> 5;
    const unsigned FULL = 0xFFFFFFFFu;
    const float* batch = pred + (size_t)b * NMS_N * 5;

    if (tid == 0) selCount = 0;
    selKeys32[tid] = 0xFFFFFFFFu;   // pre-pad: max key (e-field 2047, benign)

    // ---- Phase 1: wide vectorized load; extract 8 scores/thread ----
    float s[8];
    {
        const float4* src = (const float4*)(batch + (size_t)40 * tid);
        float4 v0 = __ldg(src + 0), v1 = __ldg(src + 1), v2 = __ldg(src + 2);
        float4 v3 = __ldg(src + 3), v5 = __ldg(src + 5), v6 = __ldg(src + 6);
        float4 v7 = __ldg(src + 7), v8 = __ldg(src + 8);
        s[0] = v0.x; s[1] = v1.y; s[2] = v2.z; s[3] = v3.w;
        s[4] = v5.x; s[5] = v6.y; s[6] = v7.z; s[7] = v8.w;
    }
    __syncthreads();   // selCount init + key pre-pad visible

    // ---- Phase 2: single-scan compaction (1 atomic per warp) ----
    {
        unsigned flags = 0;
        #pragma unroll
        for (int j = 0; j < 8; j++)
            if (s[j] >= T_SEL) flags |= 1u << j;
        int cnt = __popc(flags);
        int scan = cnt;                       // inclusive scan of per-thread counts
        #pragma unroll
        for (int d = 1; d < 32; d <<= 1) {
            int v = __shfl_up_sync(FULL, scan, d);
            if (lane >= d) scan += v;
        }
        int basep = 0;
        if (lane == 31) basep = atomicAdd(&selCount, scan);   // scan@31 = warp total
        basep = __shfl_sync(FULL, basep, 31);
        int pos = basep + scan - cnt;         // exclusive offset
        #pragma unroll
        for (int j = 0; j < 8; j++) {
            if (flags & (1u << j)) {
                if (pos < SEL_CAP) {
                    unsigned e = 8 * tid + j;
                    unsigned delta = __float_as_uint(s[j]) - U_TSEL;   // < 2^21
                    selKeys32[pos] = ((0x1FFFFFu - delta) << 11) | e;
                }
                pos++;
            }
        }
    }
    __syncthreads();
    const int nsel = selCount;
    const bool fb1 = (nsel > SEL_CAP);   // uniform across block

    if (!fb1) {
        // ---- Phase 3: counting-rank sort + fused gather/scatter (all 8 warps) ----
        {
            unsigned myKey = selKeys32[tid];
            int e = (int)(myKey & 0x7FFu);
            const float* pp = batch + (size_t)e * 5;
            float l  = __ldg(pp + 1), t  = __ldg(pp + 2);
            float r  = __ldg(pp + 3), bo = __ldg(pp + 4);
            int rank = 0;
            const uint4* keys4 = (const uint4*)selKeys32;
            #pragma unroll 16
            for (int j = 0; j < SEL_CAP / 4; j++) {
                uint4 kk = keys4[j];
                rank += (kk.x < myKey) + (kk.y < myKey)
                      + (kk.z < myKey) + (kk.w < myKey);
            }
            sortedBoxes[rank] = make_float4(l, t, r, bo);
            sortedHalf[rank]  = 0.5f * (r - l) * (bo - t);
        }
        __syncthreads();

        // ---- Phase 4: balanced triangular suppression matrix (all 8 warps) ----
        for (int slot = tid; slot < MAT_N * MAT_COLS; slot += NT) {
            int wb = slot / MAT_N;
            int i  = slot - wb * MAT_N;
            int jbase = wb << 5;
            int jend = i - jbase; jend = jend > 32 ? 32 : jend;
            unsigned mm = 0;
            if (jend > 0) {
                float4 cb = sortedBoxes[i];
                float  hh = sortedHalf[i];
                for (int jo = 0; jo < jend; jo++) {
                    if (iou_sup(sortedBoxes[jbase + jo], cb, hh)) mm |= 1u << jo;
                }
            }
            supMat[i * MAT_STRIDE + wb] = mm;
        }
        __syncthreads();

        // ---- Phase 5: bitwise greedy resolution (warp 0) ----
        if (w == 0) {
            unsigned KM0 = 0, KM1 = 0, KM2 = 0, KM3 = 0, KM4 = 0;
            int nkept = 0;
            const unsigned below = (1u << lane) - 1u;
            int matLim = nsel < MAT_N ? nsel : MAT_N;
            int nblk = (matLim + 31) >> 5;

            for (int blk = 0; blk < nblk && nkept < NMS_R; blk++) {
                int i = (blk << 5) + lane;
                bool valid = i < matLim;
                float4 cb = sortedBoxes[i];   // hoisted off the ballot chain
                const unsigned* row = supMat + i * MAT_STRIDE;
                unsigned m0 = row[0], m1 = row[1], m2 = row[2];
                unsigned m3 = row[3], m4 = row[4];
                unsigned sk = (m0 & KM0) | (m1 & KM1) | (m2 & KM2)
                            | (m3 & KM3) | (m4 & KM4);
                unsigned inb = blk == 0 ? m0 : blk == 1 ? m1 : blk == 2 ? m2
                             : blk == 3 ? m3 : m4;
                unsigned base = __ballot_sync(FULL, valid && sk == 0u);
                unsigned K = base;
                #pragma unroll 1
                for (int it = 0; it < 32; it++) {
                    bool alive = ((base >> lane) & 1u) && ((inb & K) == 0u);
                    unsigned Kn = __ballot_sync(FULL, alive);
                    if (Kn == K) break;
                    K = Kn;
                }
                bool kept = (K >> lane) & 1u;
                int  pos  = nkept + __popc(K & below);
                if (kept) keptBoxes[pos] = cb;
                if (kept && pos < NMS_R) {
                    keptVals[pos * 3 + 0] = cb.y;
                    keptVals[pos * 3 + 1] = cb.z;
                    keptVals[pos * 3 + 2] = cb.w;
                }
                KM0 |= (blk == 0) ? K : 0u; KM1 |= (blk == 1) ? K : 0u;
                KM2 |= (blk == 2) ? K : 0u; KM3 |= (blk == 3) ? K : 0u;
                KM4 |= (blk == 4) ? K : 0u;
                nkept += __popc(K);
            }

            // Continuation beyond MAT_N (rare): warp-parallel blocks.
            int cd = MAT_N;
            while (cd < nsel && nkept < NMS_R) {
                int rem = nsel - cd;
                unsigned validMask = rem >= 32 ? FULL : ((1u << rem) - 1u);
                int ci = cd + lane;
                bool valid = ci < nsel;
                int cidx = ci & (SEL_CAP - 1);
                float4 cb = sortedBoxes[cidx];
                float  hh = sortedHalf[cidx];
                bool supk = false;
                for (int kj = 0; kj < nkept; kj++)
                    supk |= iou_sup(keptBoxes[kj], cb, hh);
                unsigned supBy = 0;
                #pragma unroll 8
                for (int j = 0; j < 32; j++) {
                    int jj = (cd + j) & (SEL_CAP - 1);
                    float4 ob = sortedBoxes[jj];
                    if (iou_sup(ob, cb, hh)) supBy |= (1u << j);
                }
                supBy &= validMask & ~(1u << lane);
                unsigned base = __ballot_sync(FULL, valid && !supk);
                unsigned K = base;
                #pragma unroll 1
                for (int it = 0; it < 32; it++) {
                    bool alive = ((base >> lane) & 1u) && ((supBy & K & below) == 0u);
                    unsigned Kn = __ballot_sync(FULL, alive);
                    if (Kn == K) break;
                    K = Kn;
                }
                bool kept = (K >> lane) & 1u;
                int  pos  = nkept + __popc(K & below);
                if (kept && pos < 136) keptBoxes[pos] = cb;
                if (kept && pos < NMS_R) {
                    keptVals[pos * 3 + 0] = cb.y;
                    keptVals[pos * 3 + 1] = cb.z;
                    keptVals[pos * 3 + 2] = cb.w;
                }
                __syncwarp();
                nkept += __popc(K);
                cd += 32;
            }
            if (lane == 0) sh_nkept = (nkept < NMS_R) ? nkept : NMS_R;
        }
        __syncthreads();
    }

    // fallback condition: overflow OR too few kept (uniform decision)
    const bool fb = fb1 || (sh_nkept < NMS_R);

    // ---- Fallback: full 2048 sort + greedy (exact, rarely taken) ----
    if (fb) {
        const float4 sent = make_float4(1e30f, 1e30f, -1e30f, -1e30f);
        #pragma unroll
        for (int j = 0; j < 8; j++) {
            int e = 8 * tid + j;
            fullKeys[e] = ((ull)(~float_to_ordered(s[j])) << 32) | (unsigned)e;
        }
        __syncthreads();
        for (unsigned int k = 2; k <= NMS_N; k <<= 1) {
            for (unsigned int j = k >> 1; j > 0; j >>= 1) {
                #pragma unroll
                for (int p = 0; p < 4; p++) {
                    unsigned int i  = tid + p * NT;
                    unsigned int lo = ((i & ~(j - 1)) << 1) | (i & (j - 1));
                    unsigned int hi = lo | j;
                    ull u = fullKeys[lo], v = fullKeys[hi];
                    bool dir = ((lo & k) == 0);
                    if ((u > v) == dir) { fullKeys[lo] = v; fullKeys[hi] = u; }
                }
                __syncthreads();
            }
        }
        if (w == 0) {
            float4 k0s = sent, k1s = sent, k2s = sent, k3s = sent;
            int nkept = 0;
            int idx_n = (int)(fullKeys[0] & 0x7FF);
            const float* pn = batch + (size_t)idx_n * 5;
            float l_n = __ldg(pn + 1), t_n = __ldg(pn + 2), r_n = __ldg(pn + 3), b_n = __ldg(pn + 4);
            for (int cd = 0; cd < NMS_N && nkept < NMS_R; ++cd) {
                float4 cb = make_float4(l_n, t_n, r_n, b_n);
                if (cd + 1 < NMS_N) {
                    idx_n = (int)(fullKeys[cd + 1] & 0x7FF);
                    const float* p2 = batch + (size_t)idx_n * 5;
                    l_n = __ldg(p2 + 1); t_n = __ldg(p2 + 2); r_n = __ldg(p2 + 3); b_n = __ldg(p2 + 4);
                }
                float hh = 0.5f * (cb.z - cb.x) * (cb.w - cb.y);
                bool sup = iou_sup(k0s, cb, hh) | iou_sup(k1s, cb, hh)
                         | iou_sup(k2s, cb, hh) | iou_sup(k3s, cb, hh);
                unsigned bal = __ballot_sync(FULL, sup);
                bool keep = (bal == 0u);
                bool m = keep && ((nkept & 31) == lane);
                int  sl = nkept >> 5;
                selset(k0s, cb, m && sl == 0);
                selset(k1s, cb, m && sl == 1);
                selset(k2s, cb, m && sl == 2);
                selset(k3s, cb, m && sl == 3);
                if (keep && lane == 0) {
                    keptVals[nkept * 3 + 0] = cb.y;
                    keptVals[nkept * 3 + 1] = cb.z;
                    keptVals[nkept * 3 + 2] = cb.w;
                }
                nkept += keep ? 1 : 0;
            }
            if (lane == 0) sh_nkept = nkept;
        }
        __syncthreads();
    }

    // ---- Output: [R,3], zero-padded ----
    int nk = sh_nkept;
    for (int o = tid; o < NMS_R * 3; o += NT) {
        int slot = o / 3;
        out[(size_t)b * NMS_R * 3 + o] = (slot < nk) ? keptVals[o] : 0.0f;
    }
}

extern "C" void kernel_launch(void* const* d_in, const int* in_sizes, int n_in,
                              void* d_out, int out_size) {
    const float* pred = (const float*)d_in[0];
    float* out = (float*)d_out;
    nms_kernel<<<32, NT>>>(pred, out);
}

// round 15
// speedup vs baseline: 1.0597x; 1.0597x over previous
#include <cuda_runtime.h>
#include <cuda_bf16.h>

// NMS: B=32, N=2048, keep first R=100 surviving boxes (greedy, score-desc).
// pred: [B, N, 5] = (score, l, t, r, b);  out: [B, R, 3] = (t, r, b), zero-padded.

#define NMS_N      2048
#define NMS_R      100
#define NT         256
#define SEL_CAP    256
#define MAT_N      160
#define MAT_COLS   5
#define MAT_STRIDE 8
#define T_SEL      0.90f
#define U_TSEL     0x3F666666u   // bits of 0.90f

typedef unsigned long long ull;

__device__ __forceinline__ unsigned int float_to_ordered(float f) {
    unsigned int u = __float_as_uint(f);
    return (u & 0x80000000u) ? ~u : (u | 0x80000000u);
}

// suppress cb if inter(kb, cb) >= hh (= 0.5 * area(cb)); sentinel kb -> false
__device__ __forceinline__ bool iou_sup(const float4 kb, const float4 cb, float hh) {
    float il = fmaxf(kb.x, cb.x);
    float it = fmaxf(kb.y, cb.y);
    float ir = fminf(kb.z, cb.z);
    float ib = fminf(kb.w, cb.w);
    return fmaxf(0.0f, ir - il) * fmaxf(0.0f, ib - it) >= hh;
}
__device__ __forceinline__ void selset(float4& d, const float4 s, bool p) {
    d.x = p ? s.x : d.x; d.y = p ? s.y : d.y;
    d.z = p ? s.z : d.z; d.w = p ? s.w : d.w;
}

__global__ __launch_bounds__(NT, 1)
void nms_kernel(const float* __restrict__ pred, float* __restrict__ out) {
    // 16KB pool, aliased:
    //   fast path: selKeys32[256] (1KB @0) | supMat[160*8] (5KB @4KB)
    //   fallback : fullKeys[2048] (16KB)
    __shared__ __align__(16) ull pool[2048];
    unsigned*     selKeys32 = (unsigned*)pool;              // [256]
    unsigned int* supMat    = (unsigned int*)(pool + 512);  // [160*8], byte off 4KB, 16B-aligned rows
    ull*          fullKeys  = pool;

    __shared__ __align__(16) float4 sortedBoxes[SEL_CAP];
    __shared__ float sortedHalf[SEL_CAP];
    __shared__ __align__(16) float4 keptBoxes[136];
    __shared__ float keptVals[NMS_R * 3];   // fallback only
    __shared__ int   selCount, sh_nkept;

    const int b    = blockIdx.x;
    const int tid  = threadIdx.x;
    const int lane = tid & 31;
    const int w    = tid >> 5;
    const unsigned FULL = 0xFFFFFFFFu;
    const float* batch = pred + (size_t)b * NMS_N * 5;
    float* outb = out + (size_t)b * NMS_R * 3;

    if (tid == 0) selCount = 0;
    selKeys32[tid] = 0xFFFFFFFFu;   // pre-pad: max key (e-field 2047, benign)

    // ---- Phase 1: wide vectorized load; extract 8 scores/thread ----
    float s[8];
    {
        const float4* src = (const float4*)(batch + (size_t)40 * tid);
        float4 v0 = __ldg(src + 0), v1 = __ldg(src + 1), v2 = __ldg(src + 2);
        float4 v3 = __ldg(src + 3), v5 = __ldg(src + 5), v6 = __ldg(src + 6);
        float4 v7 = __ldg(src + 7), v8 = __ldg(src + 8);
        s[0] = v0.x; s[1] = v1.y; s[2] = v2.z; s[3] = v3.w;
        s[4] = v5.x; s[5] = v6.y; s[6] = v7.z; s[7] = v8.w;
    }
    __syncthreads();   // selCount init + key pre-pad visible

    // ---- Phase 2: single-scan compaction (1 atomic per warp) ----
    {
        unsigned flags = 0;
        #pragma unroll
        for (int j = 0; j < 8; j++)
            if (s[j] >= T_SEL) flags |= 1u << j;
        int cnt = __popc(flags);
        int scan = cnt;
        #pragma unroll
        for (int d = 1; d < 32; d <<= 1) {
            int v = __shfl_up_sync(FULL, scan, d);
            if (lane >= d) scan += v;
        }
        int basep = 0;
        if (lane == 31) basep = atomicAdd(&selCount, scan);
        basep = __shfl_sync(FULL, basep, 31);
        int pos = basep + scan - cnt;
        #pragma unroll
        for (int j = 0; j < 8; j++) {
            if (flags & (1u << j)) {
                if (pos < SEL_CAP) {
                    unsigned e = 8 * tid + j;
                    unsigned delta = __float_as_uint(s[j]) - U_TSEL;   // < 2^21
                    selKeys32[pos] = ((0x1FFFFFu - delta) << 11) | e;
                }
                pos++;
            }
        }
    }
    __syncthreads();
    const int nsel = selCount;
    const bool fb1 = (nsel > SEL_CAP);   // uniform across block

    if (!fb1) {
        // ---- Phase 3: counting-rank sort + fused gather/scatter (all 8 warps) ----
        {
            unsigned myKey = selKeys32[tid];
            int e = (int)(myKey & 0x7FFu);
            const float* pp = batch + (size_t)e * 5;
            float l  = __ldg(pp + 1), t  = __ldg(pp + 2);
            float r  = __ldg(pp + 3), bo = __ldg(pp + 4);
            int rank = 0;
            const uint4* keys4 = (const uint4*)selKeys32;
            #pragma unroll 16
            for (int j = 0; j < SEL_CAP / 4; j++) {
                uint4 kk = keys4[j];
                rank += (kk.x < myKey) + (kk.y < myKey)
                      + (kk.z < myKey) + (kk.w < myKey);
            }
            sortedBoxes[rank] = make_float4(l, t, r, bo);
            sortedHalf[rank]  = 0.5f * (r - l) * (bo - t);
        }
        __syncthreads();

        // ---- Phase 4: balanced triangular suppression matrix (all 8 warps) ----
        for (int slot = tid; slot < MAT_N * MAT_COLS; slot += NT) {
            int wb = slot / MAT_N;
            int i  = slot - wb * MAT_N;
            int jbase = wb << 5;
            int jend = i - jbase; jend = jend > 32 ? 32 : jend;
            unsigned mm = 0;
            if (jend > 0) {
                float4 cb = sortedBoxes[i];
                float  hh = sortedHalf[i];
                for (int jo = 0; jo < jend; jo++) {
                    if (iou_sup(sortedBoxes[jbase + jo], cb, hh)) mm |= 1u << jo;
                }
            }
            supMat[i * MAT_STRIDE + wb] = mm;
        }
        __syncthreads();

        // ---- Phase 5: bitwise greedy resolution (warp 0); kept triples
        //      stored DIRECTLY to global (fast path always ends at nkept==100,
        //      else fb fires and the fallback rewrites the whole output). ----
        if (w == 0) {
            unsigned KM0 = 0, KM1 = 0, KM2 = 0, KM3 = 0, KM4 = 0;
            int nkept = 0;
            const unsigned below = (1u << lane) - 1u;
            int matLim = nsel < MAT_N ? nsel : MAT_N;
            int nblk = (matLim + 31) >> 5;

            for (int blk = 0; blk < nblk && nkept < NMS_R; blk++) {
                int i = (blk << 5) + lane;
                bool valid = i < matLim;
                float4 cb = sortedBoxes[i];
                const uint4* row4 = (const uint4*)(supMat + i * MAT_STRIDE);
                uint4 r03 = row4[0];                       // cols 0-3, one LDS.128
                unsigned m4 = supMat[i * MAT_STRIDE + 4];  // col 4
                unsigned sk = (r03.x & KM0) | (r03.y & KM1) | (r03.z & KM2)
                            | (r03.w & KM3) | (m4 & KM4);
                unsigned inb = blk == 0 ? r03.x : blk == 1 ? r03.y : blk == 2 ? r03.z
                             : blk == 3 ? r03.w : m4;
                unsigned base = __ballot_sync(FULL, valid && sk == 0u);
                unsigned K = base;
                #pragma unroll 1
                for (int it = 0; it < 32; it++) {
                    bool alive = ((base >> lane) & 1u) && ((inb & K) == 0u);
                    unsigned Kn = __ballot_sync(FULL, alive);
                    if (Kn == K) break;
                    K = Kn;
                }
                bool kept = (K >> lane) & 1u;
                int  pos  = nkept + __popc(K & below);
                if (kept) keptBoxes[pos] = cb;
                if (kept && pos < NMS_R) {
                    outb[pos * 3 + 0] = cb.y;
                    outb[pos * 3 + 1] = cb.z;
                    outb[pos * 3 + 2] = cb.w;
                }
                KM0 |= (blk == 0) ? K : 0u; KM1 |= (blk == 1) ? K : 0u;
                KM2 |= (blk == 2) ? K : 0u; KM3 |= (blk == 3) ? K : 0u;
                KM4 |= (blk == 4) ? K : 0u;
                nkept += __popc(K);
            }

            // Continuation beyond MAT_N (rare): warp-parallel blocks.
            int cd = MAT_N;
            while (cd < nsel && nkept < NMS_R) {
                int rem = nsel - cd;
                unsigned validMask = rem >= 32 ? FULL : ((1u << rem) - 1u);
                int ci = cd + lane;
                bool valid = ci < nsel;
                int cidx = ci & (SEL_CAP - 1);
                float4 cb = sortedBoxes[cidx];
                float  hh = sortedHalf[cidx];
                bool supk = false;
                for (int kj = 0; kj < nkept; kj++)
                    supk |= iou_sup(keptBoxes[kj], cb, hh);
                unsigned supBy = 0;
                #pragma unroll 8
                for (int j = 0; j < 32; j++) {
                    int jj = (cd + j) & (SEL_CAP - 1);
                    float4 ob = sortedBoxes[jj];
                    if (iou_sup(ob, cb, hh)) supBy |= (1u << j);
                }
                supBy &= validMask & ~(1u << lane);
                unsigned base = __ballot_sync(FULL, valid && !supk);
                unsigned K = base;
                #pragma unroll 1
                for (int it = 0; it < 32; it++) {
                    bool alive = ((base >> lane) & 1u) && ((supBy & K & below) == 0u);
                    unsigned Kn = __ballot_sync(FULL, alive);
                    if (Kn == K) break;
                    K = Kn;
                }
                bool kept = (K >> lane) & 1u;
                int  pos  = nkept + __popc(K & below);
                if (kept && pos < 136) keptBoxes[pos] = cb;
                if (kept && pos < NMS_R) {
                    outb[pos * 3 + 0] = cb.y;
                    outb[pos * 3 + 1] = cb.z;
                    outb[pos * 3 + 2] = cb.w;
                }
                __syncwarp();
                nkept += __popc(K);
                cd += 32;
            }
            if (lane == 0) sh_nkept = (nkept < NMS_R) ? nkept : NMS_R;
        }
        __syncthreads();
    }

    // fallback condition: overflow OR too few kept (uniform decision)
    const bool fb = fb1 || (sh_nkept < NMS_R);

    // ---- Fallback: full 2048 sort + greedy (exact, rarely taken) ----
    if (fb) {
        const float4 sent = make_float4(1e30f, 1e30f, -1e30f, -1e30f);
        #pragma unroll
        for (int j = 0; j < 8; j++) {
            int e = 8 * tid + j;
            fullKeys[e] = ((ull)(~float_to_ordered(s[j])) << 32) | (unsigned)e;
        }
        __syncthreads();
        for (unsigned int k = 2; k <= NMS_N; k <<= 1) {
            for (unsigned int j = k >> 1; j > 0; j >>= 1) {
                #pragma unroll
                for (int p = 0; p < 4; p++) {
                    unsigned int i  = tid + p * NT;
                    unsigned int lo = ((i & ~(j - 1)) << 1) | (i & (j - 1));
                    unsigned int hi = lo | j;
                    ull u = fullKeys[lo], v = fullKeys[hi];
                    bool dir = ((lo & k) == 0);
                    if ((u > v) == dir) { fullKeys[lo] = v; fullKeys[hi] = u; }
                }
                __syncthreads();
            }
        }
        if (w == 0) {
            float4 k0s = sent, k1s = sent, k2s = sent, k3s = sent;
            int nkept = 0;
            int idx_n = (int)(fullKeys[0] & 0x7FF);
            const float* pn = batch + (size_t)idx_n * 5;
            float l_n = __ldg(pn + 1), t_n = __ldg(pn + 2), r_n = __ldg(pn + 3), b_n = __ldg(pn + 4);
            for (int cd = 0; cd < NMS_N && nkept < NMS_R; ++cd) {
                float4 cb = make_float4(l_n, t_n, r_n, b_n);
                if (cd + 1 < NMS_N) {
                    idx_n = (int)(fullKeys[cd + 1] & 0x7FF);
                    const float* p2 = batch + (size_t)idx_n * 5;
                    l_n = __ldg(p2 + 1); t_n = __ldg(p2 + 2); r_n = __ldg(p2 + 3); b_n = __ldg(p2 + 4);
                }
                float hh = 0.5f * (cb.z - cb.x) * (cb.w - cb.y);
                bool sup = iou_sup(k0s, cb, hh) | iou_sup(k1s, cb, hh)
                         | iou_sup(k2s, cb, hh) | iou_sup(k3s, cb, hh);
                unsigned bal = __ballot_sync(FULL, sup);
                bool keep = (bal == 0u);
                bool m = keep && ((nkept & 31) == lane);
                int  sl = nkept >> 5;
                selset(k0s, cb, m && sl == 0);
                selset(k1s, cb, m && sl == 1);
                selset(k2s, cb, m && sl == 2);
                selset(k3s, cb, m && sl == 3);
                if (keep && lane == 0) {
                    keptVals[nkept * 3 + 0] = cb.y;
                    keptVals[nkept * 3 + 1] = cb.z;
                    keptVals[nkept * 3 + 2] = cb.w;
                }
                nkept += keep ? 1 : 0;
            }
            if (lane == 0) sh_nkept = nkept;
        }
        __syncthreads();

        // fallback output: [R,3], zero-padded
        int nk = sh_nkept;
        for (int o = tid; o < NMS_R * 3; o += NT) {
            int slot = o / 3;
            outb[o] = (slot < nk) ? keptVals[o] : 0.0f;
        }
    }
}

extern "C" void kernel_launch(void* const* d_in, const int* in_sizes, int n_in,
                              void* d_out, int out_size) {
    const float* pred = (const float*)d_in[0];
    float* out = (float*)d_out;
    nms_kernel<<<32, NT>>>(pred, out);
}

// round 16
// speedup vs baseline: 1.0627x; 1.0028x over previous
#include <cuda_runtime.h>
#include <cuda_bf16.h>

// NMS: B=32, N=2048, keep first R=100 surviving boxes (greedy, score-desc).
// pred: [B, N, 5] = (score, l, t, r, b);  out: [B, R, 3] = (t, r, b), zero-padded.

#define NMS_N      2048
#define NMS_R      100
#define NT         256
#define SEL_CAP    256
#define MAT_N      160
#define MAT_COLS   5
#define MAT_STRIDE 8
#define T_SEL      0.90f
#define U_TSEL     0x3F666666u   // bits of 0.90f

typedef unsigned long long ull;

__device__ __forceinline__ unsigned int float_to_ordered(float f) {
    unsigned int u = __float_as_uint(f);
    return (u & 0x80000000u) ? ~u : (u | 0x80000000u);
}

// suppress cb if inter(kb, cb) >= hh (= 0.5 * area(cb)); sentinel kb -> false
__device__ __forceinline__ bool iou_sup(const float4 kb, const float4 cb, float hh) {
    float il = fmaxf(kb.x, cb.x);
    float it = fmaxf(kb.y, cb.y);
    float ir = fminf(kb.z, cb.z);
    float ib = fminf(kb.w, cb.w);
    return fmaxf(0.0f, ir - il) * fmaxf(0.0f, ib - it) >= hh;
}
__device__ __forceinline__ void selset(float4& d, const float4 s, bool p) {
    d.x = p ? s.x : d.x; d.y = p ? s.y : d.y;
    d.z = p ? s.z : d.z; d.w = p ? s.w : d.w;
}

__global__ __launch_bounds__(NT, 1)
void nms_kernel(const float* __restrict__ pred, float* __restrict__ out) {
    // 16KB pool, aliased:
    //   fast path: selKeys32[256] (1KB @0) | supMat/warpCnt (@4KB)
    //   fallback : fullKeys[2048] (16KB)
    __shared__ __align__(16) ull pool[2048];
    unsigned*     selKeys32 = (unsigned*)pool;              // [256]
    unsigned int* supMat    = (unsigned int*)(pool + 512);  // [160*8], byte off 4KB, 16B-aligned rows
    unsigned int* warpCnt   = (unsigned int*)(pool + 512);  // [8], dead before supMat is built
    ull*          fullKeys  = pool;

    __shared__ __align__(16) float4 sortedBoxes[SEL_CAP];
    __shared__ float sortedHalf[SEL_CAP];
    __shared__ __align__(16) float4 keptBoxes[136];
    __shared__ float keptVals[NMS_R * 3];   // fallback only
    __shared__ int   sh_nkept;

    const int b    = blockIdx.x;
    const int tid  = threadIdx.x;
    const int lane = tid & 31;
    const int w    = tid >> 5;
    const unsigned FULL = 0xFFFFFFFFu;
    const float* batch = pred + (size_t)b * NMS_N * 5;
    float* outb = out + (size_t)b * NMS_R * 3;

    selKeys32[tid] = 0xFFFFFFFFu;   // pre-pad: max key (e-field 2047, benign)

    // ---- Phase 1: wide vectorized load; extract 8 scores/thread ----
    float s[8];
    {
        const float4* src = (const float4*)(batch + (size_t)40 * tid);
        float4 v0 = __ldg(src + 0), v1 = __ldg(src + 1), v2 = __ldg(src + 2);
        float4 v3 = __ldg(src + 3), v5 = __ldg(src + 5), v6 = __ldg(src + 6);
        float4 v7 = __ldg(src + 7), v8 = __ldg(src + 8);
        s[0] = v0.x; s[1] = v1.y; s[2] = v2.z; s[3] = v3.w;
        s[4] = v5.x; s[5] = v6.y; s[6] = v7.z; s[7] = v8.w;
    }

    // ---- Phase 2a: flags + intra-warp scan; publish warp totals (no atomics) ----
    unsigned flags = 0;
    #pragma unroll
    for (int j = 0; j < 8; j++)
        if (s[j] >= T_SEL) flags |= 1u << j;
    int cnt = __popc(flags);
    int scan = cnt;
    #pragma unroll
    for (int d = 1; d < 32; d <<= 1) {
        int v = __shfl_up_sync(FULL, scan, d);
        if (lane >= d) scan += v;
    }
    if (lane == 31) warpCnt[w] = (unsigned)scan;   // warp total
    __syncthreads();   // pad + warpCnt visible

    // ---- Phase 2b: per-thread prefix over 8 warp totals; write keys ----
    int nsel;
    {
        uint4 lo = ((const uint4*)warpCnt)[0];
        uint4 hi = ((const uint4*)warpCnt)[1];
        unsigned arr[8] = {lo.x, lo.y, lo.z, lo.w, hi.x, hi.y, hi.z, hi.w};
        int basep = 0, total = 0;
        #pragma unroll
        for (int j = 0; j < 8; j++) {
            if (j < w) basep += (int)arr[j];
            total += (int)arr[j];
        }
        nsel = total;
        int pos = basep + scan - cnt;
        #pragma unroll
        for (int j = 0; j < 8; j++) {
            if (flags & (1u << j)) {
                if (pos < SEL_CAP) {
                    unsigned e = 8 * tid + j;
                    unsigned delta = __float_as_uint(s[j]) - U_TSEL;   // < 2^21
                    selKeys32[pos] = ((0x1FFFFFu - delta) << 11) | e;
                }
                pos++;
            }
        }
    }
    __syncthreads();
    const bool fb1 = (nsel > SEL_CAP);   // uniform across block

    if (!fb1) {
        // ---- Phase 3: counting-rank sort + fused gather/scatter (all 8 warps) ----
        {
            unsigned myKey = selKeys32[tid];
            int e = (int)(myKey & 0x7FFu);
            const float* pp = batch + (size_t)e * 5;
            float l  = __ldg(pp + 1), t  = __ldg(pp + 2);
            float r  = __ldg(pp + 3), bo = __ldg(pp + 4);
            int rank = 0;
            const uint4* keys4 = (const uint4*)selKeys32;
            #pragma unroll 16
            for (int j = 0; j < SEL_CAP / 4; j++) {
                uint4 kk = keys4[j];
                rank += (kk.x < myKey) + (kk.y < myKey)
                      + (kk.z < myKey) + (kk.w < myKey);
            }
            sortedBoxes[rank] = make_float4(l, t, r, bo);
            sortedHalf[rank]  = 0.5f * (r - l) * (bo - t);
        }
        __syncthreads();

        // ---- Phase 4: balanced triangular suppression matrix (all 8 warps) ----
        for (int slot = tid; slot < MAT_N * MAT_COLS; slot += NT) {
            int wb = slot / MAT_N;
            int i  = slot - wb * MAT_N;
            int jbase = wb << 5;
            int jend = i - jbase; jend = jend > 32 ? 32 : jend;
            unsigned mm = 0;
            if (jend > 0) {
                float4 cb = sortedBoxes[i];
                float  hh = sortedHalf[i];
                for (int jo = 0; jo < jend; jo++) {
                    if (iou_sup(sortedBoxes[jbase + jo], cb, hh)) mm |= 1u << jo;
                }
            }
            supMat[i * MAT_STRIDE + wb] = mm;
        }
        __syncthreads();

        // ---- Phase 5: bitwise greedy resolution (warp 0); next-block rows
        //      prefetched ahead of the ballot chain; kept triples stored
        //      directly to global (fast path always reaches nkept==100,
        //      else fb fires and the fallback rewrites the whole output). ----
        if (w == 0) {
            unsigned KM0 = 0, KM1 = 0, KM2 = 0, KM3 = 0, KM4 = 0;
            int nkept = 0;
            const unsigned below = (1u << lane) - 1u;
            int matLim = nsel < MAT_N ? nsel : MAT_N;
            int nblk = (matLim + 31) >> 5;

            // prefetch block 0
            uint4    r03 = ((const uint4*)(supMat + lane * MAT_STRIDE))[0];
            unsigned m4  = supMat[lane * MAT_STRIDE + 4];
            float4   cb  = sortedBoxes[lane];

            for (int blk = 0; blk < nblk && nkept < NMS_R; blk++) {
                int i = (blk << 5) + lane;
                bool valid = i < matLim;
                uint4 cr03 = r03; unsigned cm4 = m4; float4 ccb = cb;
                // prefetch next block (K-independent; wraps benignly on last)
                {
                    int inx = (((blk + 1) < nblk ? (blk + 1) : 0) << 5) + lane;
                    r03 = ((const uint4*)(supMat + inx * MAT_STRIDE))[0];
                    m4  = supMat[inx * MAT_STRIDE + 4];
                    cb  = sortedBoxes[inx];
                }
                unsigned sk = (cr03.x & KM0) | (cr03.y & KM1) | (cr03.z & KM2)
                            | (cr03.w & KM3) | (cm4 & KM4);
                unsigned inb = blk == 0 ? cr03.x : blk == 1 ? cr03.y : blk == 2 ? cr03.z
                             : blk == 3 ? cr03.w : cm4;
                unsigned base = __ballot_sync(FULL, valid && sk == 0u);
                unsigned K = base;
                #pragma unroll 1
                for (int it = 0; it < 32; it++) {
                    bool alive = ((base >> lane) & 1u) && ((inb & K) == 0u);
                    unsigned Kn = __ballot_sync(FULL, alive);
                    if (Kn == K) break;
                    K = Kn;
                }
                bool kept = (K >> lane) & 1u;
                int  pos  = nkept + __popc(K & below);
                if (kept) keptBoxes[pos] = ccb;
                if (kept && pos < NMS_R) {
                    outb[pos * 3 + 0] = ccb.y;
                    outb[pos * 3 + 1] = ccb.z;
                    outb[pos * 3 + 2] = ccb.w;
                }
                KM0 |= (blk == 0) ? K : 0u; KM1 |= (blk == 1) ? K : 0u;
                KM2 |= (blk == 2) ? K : 0u; KM3 |= (blk == 3) ? K : 0u;
                KM4 |= (blk == 4) ? K : 0u;
                nkept += __popc(K);
            }

            // Continuation beyond MAT_N (rare): warp-parallel blocks.
            int cd = MAT_N;
            while (cd < nsel && nkept < NMS_R) {
                int rem = nsel - cd;
                unsigned validMask = rem >= 32 ? FULL : ((1u << rem) - 1u);
                int ci = cd + lane;
                bool valid = ci < nsel;
                int cidx = ci & (SEL_CAP - 1);
                float4 xb = sortedBoxes[cidx];
                float  hh = sortedHalf[cidx];
                bool supk = false;
                for (int kj = 0; kj < nkept; kj++)
                    supk |= iou_sup(keptBoxes[kj], xb, hh);
                unsigned supBy = 0;
                #pragma unroll 8
                for (int j = 0; j < 32; j++) {
                    int jj = (cd + j) & (SEL_CAP - 1);
                    float4 ob = sortedBoxes[jj];
                    if (iou_sup(ob, xb, hh)) supBy |= (1u << j);
                }
                supBy &= validMask & ~(1u << lane);
                unsigned base = __ballot_sync(FULL, valid && !supk);
                unsigned K = base;
                #pragma unroll 1
                for (int it = 0; it < 32; it++) {
                    bool alive = ((base >> lane) & 1u) && ((supBy & K & below) == 0u);
                    unsigned Kn = __ballot_sync(FULL, alive);
                    if (Kn == K) break;
                    K = Kn;
                }
                bool kept = (K >> lane) & 1u;
                int  pos  = nkept + __popc(K & below);
                if (kept && pos < 136) keptBoxes[pos] = xb;
                if (kept && pos < NMS_R) {
                    outb[pos * 3 + 0] = xb.y;
                    outb[pos * 3 + 1] = xb.z;
                    outb[pos * 3 + 2] = xb.w;
                }
                __syncwarp();
                nkept += __popc(K);
                cd += 32;
            }
            if (lane == 0) sh_nkept = (nkept < NMS_R) ? nkept : NMS_R;
        }
        __syncthreads();
    }

    // fallback condition: overflow OR too few kept (uniform decision)
    const bool fb = fb1 || (sh_nkept < NMS_R);

    // ---- Fallback: full 2048 sort + greedy (exact, rarely taken) ----
    if (fb) {
        const float4 sent = make_float4(1e30f, 1e30f, -1e30f, -1e30f);
        #pragma unroll
        for (int j = 0; j < 8; j++) {
            int e = 8 * tid + j;
            fullKeys[e] = ((ull)(~float_to_ordered(s[j])) << 32) | (unsigned)e;
        }
        __syncthreads();
        for (unsigned int k = 2; k <= NMS_N; k <<= 1) {
            for (unsigned int j = k >> 1; j > 0; j >>= 1) {
                #pragma unroll
                for (int p = 0; p < 4; p++) {
                    unsigned int i  = tid + p * NT;
                    unsigned int lo = ((i & ~(j - 1)) << 1) | (i & (j - 1));
                    unsigned int hi = lo | j;
                    ull u = fullKeys[lo], v = fullKeys[hi];
                    bool dir = ((lo & k) == 0);
                    if ((u > v) == dir) { fullKeys[lo] = v; fullKeys[hi] = u; }
                }
                __syncthreads();
            }
        }
        if (w == 0) {
            float4 k0s = sent, k1s = sent, k2s = sent, k3s = sent;
            int nkept = 0;
            int idx_n = (int)(fullKeys[0] & 0x7FF);
            const float* pn = batch + (size_t)idx_n * 5;
            float l_n = __ldg(pn + 1), t_n = __ldg(pn + 2), r_n = __ldg(pn + 3), b_n = __ldg(pn + 4);
            for (int cd = 0; cd < NMS_N && nkept < NMS_R; ++cd) {
                float4 cb = make_float4(l_n, t_n, r_n, b_n);
                if (cd + 1 < NMS_N) {
                    idx_n = (int)(fullKeys[cd + 1] & 0x7FF);
                    const float* p2 = batch + (size_t)idx_n * 5;
                    l_n = __ldg(p2 + 1); t_n = __ldg(p2 + 2); r_n = __ldg(p2 + 3); b_n = __ldg(p2 + 4);
                }
                float hh = 0.5f * (cb.z - cb.x) * (cb.w - cb.y);
                bool sup = iou_sup(k0s, cb, hh) | iou_sup(k1s, cb, hh)
                         | iou_sup(k2s, cb, hh) | iou_sup(k3s, cb, hh);
                unsigned bal = __ballot_sync(FULL, sup);
                bool keep = (bal == 0u);
                bool m = keep && ((nkept & 31) == lane);
                int  sl = nkept >> 5;
                selset(k0s, cb, m && sl == 0);
                selset(k1s, cb, m && sl == 1);
                selset(k2s, cb, m && sl == 2);
                selset(k3s, cb, m && sl == 3);
                if (keep && lane == 0) {
                    keptVals[nkept * 3 + 0] = cb.y;
                    keptVals[nkept * 3 + 1] = cb.z;
                    keptVals[nkept * 3 + 2] = cb.w;
                }
                nkept += keep ? 1 : 0;
            }
            if (lane == 0) sh_nkept = nkept;
        }
        __syncthreads();

        // fallback output: [R,3], zero-padded
        int nk = sh_nkept;
        for (int o = tid; o < NMS_R * 3; o += NT) {
            int slot = o / 3;
            outb[o] = (slot < nk) ? keptVals[o] : 0.0f;
        }
    }
}

extern "C" void kernel_launch(void* const* d_in, const int* in_sizes, int n_in,
                              void* d_out, int out_size) {
    const float* pred = (const float*)d_in[0];
    float* out = (float*)d_out;
    nms_kernel<<<32, NT>>>(pred, out);
}

// round 17
// speedup vs baseline: 1.1235x; 1.0572x over previous
#include <cuda_runtime.h>
#include <cuda_bf16.h>

// NMS: B=32, N=2048, keep first R=100 surviving boxes (greedy, score-desc).
// pred: [B, N, 5] = (score, l, t, r, b);  out: [B, R, 3] = (t, r, b), zero-padded.

#define NMS_N      2048
#define NMS_R      100
#define NT         512
#define SEL_CAP    256
#define MAT_N      160
#define MAT_COLS   5
#define MAT_STRIDE 8
#define T_SEL      0.90f
#define U_TSEL     0x3F666666u   // bits of 0.90f

typedef unsigned long long ull;

__device__ __forceinline__ unsigned int float_to_ordered(float f) {
    unsigned int u = __float_as_uint(f);
    return (u & 0x80000000u) ? ~u : (u | 0x80000000u);
}

// suppress cb if inter(kb, cb) >= hh (= 0.5 * area(cb)); sentinel kb -> false
__device__ __forceinline__ bool iou_sup(const float4 kb, const float4 cb, float hh) {
    float il = fmaxf(kb.x, cb.x);
    float it = fmaxf(kb.y, cb.y);
    float ir = fminf(kb.z, cb.z);
    float ib = fminf(kb.w, cb.w);
    return fmaxf(0.0f, ir - il) * fmaxf(0.0f, ib - it) >= hh;
}
__device__ __forceinline__ void selset(float4& d, const float4 s, bool p) {
    d.x = p ? s.x : d.x; d.y = p ? s.y : d.y;
    d.z = p ? s.z : d.z; d.w = p ? s.w : d.w;
}

__global__ __launch_bounds__(NT, 1)
void nms_kernel(const float* __restrict__ pred, float* __restrict__ out) {
    // 16KB pool, aliased:
    //   fast path: selKeys32[256] (1KB @0) | rankPart[256] (1KB @1KB)
    //              | warpCnt[16]/supMat[160*8] (@4KB)
    //   fallback : fullKeys[2048] (16KB)
    __shared__ __align__(16) ull pool[2048];
    unsigned*     selKeys32 = (unsigned*)pool;                     // [256] @0
    unsigned int* rankPart  = (unsigned int*)((char*)pool + 1024); // [256] @1KB
    unsigned int* supMat    = (unsigned int*)(pool + 512);         // [160*8] @4KB, 16B rows
    unsigned int* warpCnt   = (unsigned int*)(pool + 512);         // [16], dead before supMat
    ull*          fullKeys  = pool;

    __shared__ __align__(16) float4 sortedBoxes[SEL_CAP];
    __shared__ float sortedHalf[SEL_CAP];
    __shared__ __align__(16) float4 keptBoxes[136];
    __shared__ float keptVals[NMS_R * 3];   // fallback only
    __shared__ int   sh_nkept;

    const int b    = blockIdx.x;
    const int tid  = threadIdx.x;
    const int lane = tid & 31;
    const int w    = tid >> 5;
    const unsigned FULL = 0xFFFFFFFFu;
    const float* batch = pred + (size_t)b * NMS_N * 5;
    float* outb = out + (size_t)b * NMS_R * 3;

    if (tid < SEL_CAP) selKeys32[tid] = 0xFFFFFFFFu;   // pre-pad: max key

    // ---- Phase 1: wide vectorized load; 4 boxes (5 x float4) per thread ----
    float s[4];
    {
        const float4* src = (const float4*)(batch + (size_t)20 * tid);
        float4 v0 = __ldg(src + 0), v1 = __ldg(src + 1);
        float4 v2 = __ldg(src + 2), v3 = __ldg(src + 3);
        (void)__ldg(src + 4);   // covers box3 tail (t,r,b) — not needed for score
        s[0] = v0.x; s[1] = v1.y; s[2] = v2.z; s[3] = v3.w;
    }

    // ---- Phase 2a: flags + intra-warp scan; publish warp totals (no atomics) ----
    unsigned flags = 0;
    #pragma unroll
    for (int j = 0; j < 4; j++)
        if (s[j] >= T_SEL) flags |= 1u << j;
    int cnt = __popc(flags);
    int scan = cnt;
    #pragma unroll
    for (int d = 1; d < 32; d <<= 1) {
        int v = __shfl_up_sync(FULL, scan, d);
        if (lane >= d) scan += v;
    }
    if (lane == 31) warpCnt[w] = (unsigned)scan;   // warp total
    __syncthreads();   // pad + warpCnt visible

    // ---- Phase 2b: per-thread prefix over 16 warp totals; write keys ----
    int nsel;
    {
        int basep = 0, total = 0;
        #pragma unroll
        for (int j = 0; j < 16; j++) {
            int v = (int)warpCnt[j];
            if (j < w) basep += v;
            total += v;
        }
        nsel = total;
        int pos = basep + scan - cnt;
        #pragma unroll
        for (int j = 0; j < 4; j++) {
            if (flags & (1u << j)) {
                if (pos < SEL_CAP) {
                    unsigned e = 4 * tid + j;
                    unsigned delta = __float_as_uint(s[j]) - U_TSEL;   // < 2^21
                    selKeys32[pos] = ((0x1FFFFFu - delta) << 11) | e;
                }
                pos++;
            }
        }
    }
    __syncthreads();
    const bool fb1 = (nsel > SEL_CAP);   // uniform across block

    if (!fb1) {
        // ---- Phase 3: split counting-rank (2 threads per key) + fused gather ----
        // thread t (<256): key t, scans keys [0,128), gathers box, scatters.
        // thread t+256   : key t, scans keys [128,256) -> rankPart[t].
        {
            int key_id = tid & 255;
            bool upper = tid >= 256;
            unsigned myKey = selKeys32[key_id];
            const uint4* keys4 = (const uint4*)selKeys32 + (upper ? 32 : 0);
            int rank = 0;
            #pragma unroll 8
            for (int j = 0; j < 32; j++) {
                uint4 kk = keys4[j];
                rank += (kk.x < myKey) + (kk.y < myKey)
                      + (kk.z < myKey) + (kk.w < myKey);
            }
            float l = 0, t = 0, r = 0, bo = 0;
            if (upper) {
                rankPart[key_id] = (unsigned)rank;
            } else {
                int e = (int)(myKey & 0x7FFu);
                const float* pp = batch + (size_t)e * 5;
                l = __ldg(pp + 1); t = __ldg(pp + 2);
                r = __ldg(pp + 3); bo = __ldg(pp + 4);
            }
            __syncthreads();
            if (!upper) {
                int rk = rank + (int)rankPart[key_id];
                sortedBoxes[rk] = make_float4(l, t, r, bo);
                sortedHalf[rk]  = 0.5f * (r - l) * (bo - t);
            }
        }
        __syncthreads();

        // ---- Phase 4: balanced triangular suppression matrix (16 warps) ----
        for (int slot = tid; slot < MAT_N * MAT_COLS; slot += NT) {
            int wb = slot / MAT_N;
            int i  = slot - wb * MAT_N;
            int jbase = wb << 5;
            int jend = i - jbase; jend = jend > 32 ? 32 : jend;
            unsigned mm = 0;
            if (jend > 0) {
                float4 cb = sortedBoxes[i];
                float  hh = sortedHalf[i];
                for (int jo = 0; jo < jend; jo++) {
                    if (iou_sup(sortedBoxes[jbase + jo], cb, hh)) mm |= 1u << jo;
                }
            }
            supMat[i * MAT_STRIDE + wb] = mm;
        }
        __syncthreads();

        // ---- Phase 5: bitwise greedy resolution (warp 0); prefetched rows;
        //      kept triples stored directly to global. ----
        if (w == 0) {
            unsigned KM0 = 0, KM1 = 0, KM2 = 0, KM3 = 0, KM4 = 0;
            int nkept = 0;
            const unsigned below = (1u << lane) - 1u;
            int matLim = nsel < MAT_N ? nsel : MAT_N;
            int nblk = (matLim + 31) >> 5;

            uint4    r03 = ((const uint4*)(supMat + lane * MAT_STRIDE))[0];
            unsigned m4  = supMat[lane * MAT_STRIDE + 4];
            float4   cb  = sortedBoxes[lane];

            for (int blk = 0; blk < nblk && nkept < NMS_R; blk++) {
                int i = (blk << 5) + lane;
                bool valid = i < matLim;
                uint4 cr03 = r03; unsigned cm4 = m4; float4 ccb = cb;
                {
                    int inx = (((blk + 1) < nblk ? (blk + 1) : 0) << 5) + lane;
                    r03 = ((const uint4*)(supMat + inx * MAT_STRIDE))[0];
                    m4  = supMat[inx * MAT_STRIDE + 4];
                    cb  = sortedBoxes[inx];
                }
                unsigned sk = (cr03.x & KM0) | (cr03.y & KM1) | (cr03.z & KM2)
                            | (cr03.w & KM3) | (cm4 & KM4);
                unsigned inb = blk == 0 ? cr03.x : blk == 1 ? cr03.y : blk == 2 ? cr03.z
                             : blk == 3 ? cr03.w : cm4;
                unsigned base = __ballot_sync(FULL, valid && sk == 0u);
                unsigned K = base;
                #pragma unroll 1
                for (int it = 0; it < 32; it++) {
                    bool alive = ((base >> lane) & 1u) && ((inb & K) == 0u);
                    unsigned Kn = __ballot_sync(FULL, alive);
                    if (Kn == K) break;
                    K = Kn;
                }
                bool kept = (K >> lane) & 1u;
                int  pos  = nkept + __popc(K & below);
                if (kept) keptBoxes[pos] = ccb;
                if (kept && pos < NMS_R) {
                    outb[pos * 3 + 0] = ccb.y;
                    outb[pos * 3 + 1] = ccb.z;
                    outb[pos * 3 + 2] = ccb.w;
                }
                KM0 |= (blk == 0) ? K : 0u; KM1 |= (blk == 1) ? K : 0u;
                KM2 |= (blk == 2) ? K : 0u; KM3 |= (blk == 3) ? K : 0u;
                KM4 |= (blk == 4) ? K : 0u;
                nkept += __popc(K);
            }

            // Continuation beyond MAT_N (rare): warp-parallel blocks.
            int cd = MAT_N;
            while (cd < nsel && nkept < NMS_R) {
                int rem = nsel - cd;
                unsigned validMask = rem >= 32 ? FULL : ((1u << rem) - 1u);
                int ci = cd + lane;
                bool valid = ci < nsel;
                int cidx = ci & (SEL_CAP - 1);
                float4 xb = sortedBoxes[cidx];
                float  hh = sortedHalf[cidx];
                bool supk = false;
                for (int kj = 0; kj < nkept; kj++)
                    supk |= iou_sup(keptBoxes[kj], xb, hh);
                unsigned supBy = 0;
                #pragma unroll 8
                for (int j = 0; j < 32; j++) {
                    int jj = (cd + j) & (SEL_CAP - 1);
                    float4 ob = sortedBoxes[jj];
                    if (iou_sup(ob, xb, hh)) supBy |= (1u << j);
                }
                supBy &= validMask & ~(1u << lane);
                unsigned base = __ballot_sync(FULL, valid && !supk);
                unsigned K = base;
                #pragma unroll 1
                for (int it = 0; it < 32; it++) {
                    bool alive = ((base >> lane) & 1u) && ((supBy & K & below) == 0u);
                    unsigned Kn = __ballot_sync(FULL, alive);
                    if (Kn == K) break;
                    K = Kn;
                }
                bool kept = (K >> lane) & 1u;
                int  pos  = nkept + __popc(K & below);
                if (kept && pos < 136) keptBoxes[pos] = xb;
                if (kept && pos < NMS_R) {
                    outb[pos * 3 + 0] = xb.y;
                    outb[pos * 3 + 1] = xb.z;
                    outb[pos * 3 + 2] = xb.w;
                }
                __syncwarp();
                nkept += __popc(K);
                cd += 32;
            }
            if (lane == 0) sh_nkept = (nkept < NMS_R) ? nkept : NMS_R;
        }
        __syncthreads();
    }

    // fallback condition: overflow OR too few kept (uniform decision)
    const bool fb = fb1 || (sh_nkept < NMS_R);

    // ---- Fallback: full 2048 sort + greedy (exact, rarely taken) ----
    if (fb) {
        const float4 sent = make_float4(1e30f, 1e30f, -1e30f, -1e30f);
        #pragma unroll
        for (int j = 0; j < 4; j++) {
            int e = 4 * tid + j;
            fullKeys[e] = ((ull)(~float_to_ordered(s[j])) << 32) | (unsigned)e;
        }
        __syncthreads();
        for (unsigned int k = 2; k <= NMS_N; k <<= 1) {
            for (unsigned int j = k >> 1; j > 0; j >>= 1) {
                #pragma unroll
                for (int p = 0; p < 2; p++) {
                    unsigned int i  = tid + p * NT;
                    unsigned int lo = ((i & ~(j - 1)) << 1) | (i & (j - 1));
                    unsigned int hi = lo | j;
                    ull u = fullKeys[lo], v = fullKeys[hi];
                    bool dir = ((lo & k) == 0);
                    if ((u > v) == dir) { fullKeys[lo] = v; fullKeys[hi] = u; }
                }
                __syncthreads();
            }
        }
        if (w == 0) {
            float4 k0s = sent, k1s = sent, k2s = sent, k3s = sent;
            int nkept = 0;
            int idx_n = (int)(fullKeys[0] & 0x7FF);
            const float* pn = batch + (size_t)idx_n * 5;
            float l_n = __ldg(pn + 1), t_n = __ldg(pn + 2), r_n = __ldg(pn + 3), b_n = __ldg(pn + 4);
            for (int cd = 0; cd < NMS_N && nkept < NMS_R; ++cd) {
                float4 cb = make_float4(l_n, t_n, r_n, b_n);
                if (cd + 1 < NMS_N) {
                    idx_n = (int)(fullKeys[cd + 1] & 0x7FF);
                    const float* p2 = batch + (size_t)idx_n * 5;
                    l_n = __ldg(p2 + 1); t_n = __ldg(p2 + 2); r_n = __ldg(p2 + 3); b_n = __ldg(p2 + 4);
                }
                float hh = 0.5f * (cb.z - cb.x) * (cb.w - cb.y);
                bool sup = iou_sup(k0s, cb, hh) | iou_sup(k1s, cb, hh)
                         | iou_sup(k2s, cb, hh) | iou_sup(k3s, cb, hh);
                unsigned bal = __ballot_sync(FULL, sup);
                bool keep = (bal == 0u);
                bool m = keep && ((nkept & 31) == lane);
                int  sl = nkept >> 5;
                selset(k0s, cb, m && sl == 0);
                selset(k1s, cb, m && sl == 1);
                selset(k2s, cb, m && sl == 2);
                selset(k3s, cb, m && sl == 3);
                if (keep && lane == 0) {
                    keptVals[nkept * 3 + 0] = cb.y;
                    keptVals[nkept * 3 + 1] = cb.z;
                    keptVals[nkept * 3 + 2] = cb.w;
                }
                nkept += keep ? 1 : 0;
            }
            if (lane == 0) sh_nkept = nkept;
        }
        __syncthreads();

        // fallback output: [R,3], zero-padded
        int nk = sh_nkept;
        if (tid < NMS_R * 3) {
            int slot = tid / 3;
            outb[tid] = (slot < nk) ? keptVals[tid] : 0.0f;
        }
    }
}

extern "C" void kernel_launch(void* const* d_in, const int* in_sizes, int n_in,
                              void* d_out, int out_size) {
    const float* pred = (const float*)d_in[0];
    float* out = (float*)d_out;
    nms_kernel<<<32, NT>>>(pred, out);
}